// round 6
// baseline (speedup 1.0000x reference)
#include <cuda_runtime.h>
#include <cuda_bf16.h>

// ---------------------------------------------------------------------------
// GCN: 3x GCNConv (64->64->64->32) + global mean pool over 64 graphs.
// ELL-by-dst gather formulation, dinv folded into the GEMM epilogue:
//   g[i]   = dinv[i] * (act(prev[i] + b) @ W)      dinv = rsqrt(deg+1)
//   out[r] = dinv[r] * (g[r] + sum_{e: dst=r} g[src(e)])
// ---------------------------------------------------------------------------

#define N_MAX 100000
#define E_MAX 1600000
#define G_MAX 64
#define CAP   128          // ELL row capacity (Poisson(16) => P(deg>128) ~ 0)
#define FULL  0xffffffffu

__device__ int   g_is64;
__device__ int   g_cursor[N_MAX];                 // per-row edge count
__device__ int   g_col[(size_t)N_MAX * CAP];      // ELL column indices
__device__ float g_bufA[(size_t)N_MAX * 64];
__device__ float g_bufB[(size_t)N_MAX * 64];
__device__ float g_sums[G_MAX * 32];
__device__ int   g_cnt[G_MAX];

__device__ __forceinline__ int load_idx(const void* p, long long i, int is64) {
    if (is64) return (int)(((const long long*)p)[i]);
    return ((const int*)p)[i];
}

// ---- init: zero cursors/pool + dtype detection (block 0) -------------------
__global__ void k_init(const unsigned int* w, int npairs, int N) {
    int i = blockIdx.x * blockDim.x + threadIdx.x;
    if (i < N) g_cursor[i] = 0;
    if (i < G_MAX * 32) g_sums[i] = 0.0f;
    if (i < G_MAX) g_cnt[i] = 0;
    if (blockIdx.x == 0) {
        __shared__ int any;
        if (threadIdx.x == 0) any = 0;
        __syncthreads();
        for (int k = threadIdx.x; k < npairs; k += blockDim.x)
            if (w[2 * k + 1] != 0u) any = 1;
        __syncthreads();
        if (threadIdx.x == 0) g_is64 = (any == 0) ? 1 : 0;
    }
}

// ---- ELL fill: one pass over edges -----------------------------------------
__global__ void k_fill_ell(const void* ei, int E) {
    int e = blockIdx.x * blockDim.x + threadIdx.x;
    if (e >= E) return;
    int is64 = g_is64;
    int s = load_idx(ei, e, is64);
    int d = load_idx(ei, (long long)E + e, is64);
    int pos = atomicAdd(&g_cursor[d], 1);
    if (pos < CAP) g_col[(size_t)d * CAP + pos] = s;
}

// ---- GEMM: out[n] = dinv[n] * (act(in[n] + bprev) @ W) ---------------------
// MODE 0: identity.  MODE 1: relu(in + b).  MODE 2: in + b.
// FOUT/32 threads per node, 32 accumulators each, W in smem (broadcast reads).
template <int FOUT, int MODE>
__global__ __launch_bounds__(256)
void k_gemm2(const float* __restrict__ in, const float* __restrict__ W,
             const float* __restrict__ bprev, float* __restrict__ out, int N) {
    const int TPN = FOUT / 32;            // threads per node: 2 (F=64) or 1
    const int NPB = 256 / TPN;            // nodes per block
    __shared__ float Ws[64 * FOUT];

    for (int i = threadIdx.x; i < 64 * FOUT / 4; i += 256)
        reinterpret_cast<float4*>(Ws)[i] =
            reinterpret_cast<const float4*>(W)[i];
    __syncthreads();

    int n    = blockIdx.x * NPB + threadIdx.x / TPN;
    int half = (TPN == 2) ? (threadIdx.x & 1) : 0;
    if (n >= N) return;

    float acc[32];
#pragma unroll
    for (int j = 0; j < 32; j++) acc[j] = 0.f;

    const float* xr = in + (size_t)n * 64;

    for (int c = 0; c < 4; c++) {                 // chunks of 16 k
        float4 xv[4];
#pragma unroll
        for (int i = 0; i < 4; i++) {
            xv[i] = *reinterpret_cast<const float4*>(xr + 16 * c + 4 * i);
            if (MODE != 0) {
                float4 b4 = __ldg(reinterpret_cast<const float4*>(bprev) + 4 * c + i);
                xv[i].x += b4.x; xv[i].y += b4.y;
                xv[i].z += b4.z; xv[i].w += b4.w;
                if (MODE == 1) {
                    xv[i].x = fmaxf(xv[i].x, 0.f); xv[i].y = fmaxf(xv[i].y, 0.f);
                    xv[i].z = fmaxf(xv[i].z, 0.f); xv[i].w = fmaxf(xv[i].w, 0.f);
                }
            }
        }
        const float* wb = Ws + (size_t)(16 * c) * FOUT + half * 32;
#pragma unroll
        for (int kk = 0; kk < 16; kk++) {
            float xk = reinterpret_cast<const float*>(xv)[kk];
            const float4* wr = reinterpret_cast<const float4*>(wb + kk * FOUT);
#pragma unroll
            for (int j = 0; j < 8; j++) {
                float4 wv = wr[j];
                acc[4 * j + 0] += xk * wv.x;
                acc[4 * j + 1] += xk * wv.y;
                acc[4 * j + 2] += xk * wv.z;
                acc[4 * j + 3] += xk * wv.w;
            }
        }
    }

    float dr = rsqrtf((float)(__ldg(&g_cursor[n]) + 1));   // dinv[n]
    float* outp = out + (size_t)n * FOUT + half * 32;
#pragma unroll
    for (int j = 0; j < 8; j++) {
        float4 o = make_float4(dr * acc[4 * j + 0], dr * acc[4 * j + 1],
                               dr * acc[4 * j + 2], dr * acc[4 * j + 3]);
        *reinterpret_cast<float4*>(outp + 4 * j) = o;
    }
}

// ---- SpMM (ELL): warp per (row, 32-feature half) ---------------------------
// out[r] = dinv[r] * (g[r] + sum g[col[e]]);  each gather = one 128B line.
template <int F>
__global__ __launch_bounds__(256)
void k_spmm(const float* __restrict__ g, float* __restrict__ out, int N) {
    const int WPR = F / 32;
    int gw   = (blockIdx.x * 256 + threadIdx.x) >> 5;
    int row  = gw / WPR;
    int half = gw % WPR;
    if (row >= N) return;
    int lane = threadIdx.x & 31;

    int degT = __ldg(&g_cursor[row]);
    int deg  = (degT < CAP) ? degT : CAP;
    float dr = rsqrtf((float)(degT + 1));

    const float* __restrict__ gb = g + half * 32 + lane;
    float acc = __ldg(&gb[(size_t)row * F]);            // self loop
    const int* cp = g_col + (size_t)row * CAP;

    for (int e = 0; e < deg; e += 32) {
        int nn = deg - e; if (nn > 32) nn = 32;
        int myc = (lane < nn) ? __ldg(&cp[e + lane]) : 0;
        int j = 0;
        for (; j + 8 <= nn; j += 8) {
            int c0 = __shfl_sync(FULL, myc, j + 0);
            int c1 = __shfl_sync(FULL, myc, j + 1);
            int c2 = __shfl_sync(FULL, myc, j + 2);
            int c3 = __shfl_sync(FULL, myc, j + 3);
            int c4 = __shfl_sync(FULL, myc, j + 4);
            int c5 = __shfl_sync(FULL, myc, j + 5);
            int c6 = __shfl_sync(FULL, myc, j + 6);
            int c7 = __shfl_sync(FULL, myc, j + 7);
            float v0 = __ldg(&gb[(size_t)c0 * F]);
            float v1 = __ldg(&gb[(size_t)c1 * F]);
            float v2 = __ldg(&gb[(size_t)c2 * F]);
            float v3 = __ldg(&gb[(size_t)c3 * F]);
            float v4 = __ldg(&gb[(size_t)c4 * F]);
            float v5 = __ldg(&gb[(size_t)c5 * F]);
            float v6 = __ldg(&gb[(size_t)c6 * F]);
            float v7 = __ldg(&gb[(size_t)c7 * F]);
            float s0 = v0 + v1, s1 = v2 + v3, s2 = v4 + v5, s3 = v6 + v7;
            acc += (s0 + s1) + (s2 + s3);
        }
        for (; j + 4 <= nn; j += 4) {
            int c0 = __shfl_sync(FULL, myc, j + 0);
            int c1 = __shfl_sync(FULL, myc, j + 1);
            int c2 = __shfl_sync(FULL, myc, j + 2);
            int c3 = __shfl_sync(FULL, myc, j + 3);
            float v0 = __ldg(&gb[(size_t)c0 * F]);
            float v1 = __ldg(&gb[(size_t)c1 * F]);
            float v2 = __ldg(&gb[(size_t)c2 * F]);
            float v3 = __ldg(&gb[(size_t)c3 * F]);
            acc += (v0 + v1) + (v2 + v3);
        }
        for (; j < nn; j++) {
            int c = __shfl_sync(FULL, myc, j);
            acc += __ldg(&gb[(size_t)c * F]);
        }
    }

    out[(size_t)row * F + half * 32 + lane] = dr * acc;
}

// ---- pooling ---------------------------------------------------------------
__global__ void k_pool_acc(const float* __restrict__ agg, const void* batch,
                           int N) {
    int idx = blockIdx.x * blockDim.x + threadIdx.x;
    if (idx >= N * 32) return;
    int n = idx >> 5;
    int f = idx & 31;
    int b = load_idx(batch, n, g_is64);
    atomicAdd(&g_sums[b * 32 + f], agg[(size_t)n * 32 + f]);
    if (f == 0) atomicAdd(&g_cnt[b], 1);
}

__global__ void k_pool_out(float* __restrict__ out,
                           const float* __restrict__ b3) {
    int i = blockIdx.x * blockDim.x + threadIdx.x;
    if (i >= G_MAX * 32) return;
    int f = i & 31;
    float c = fmaxf((float)g_cnt[i >> 5], 1.0f);
    out[i] = g_sums[i] / c + __ldg(&b3[f]);
}

// ---------------------------------------------------------------------------
extern "C" void kernel_launch(void* const* d_in, const int* in_sizes, int n_in,
                              void* d_out, int out_size) {
    int N = in_sizes[0] / 64;
    int E = in_sizes[1] / 2;
    if (N > N_MAX) N = N_MAX;
    if (E > E_MAX) E = E_MAX;

    int base = 3;
    if (n_in >= 10 && in_sizes[3] == 1) base = 4;

    const float* x     = (const float*)d_in[0];
    const void*  ei    = d_in[1];
    const void*  batch = d_in[2];
    const float* W1 = (const float*)d_in[base + 0];
    const float* b1 = (const float*)d_in[base + 1];
    const float* W2 = (const float*)d_in[base + 2];
    const float* b2 = (const float*)d_in[base + 3];
    const float* W3 = (const float*)d_in[base + 4];
    const float* b3 = (const float*)d_in[base + 5];
    float* out = (float*)d_out;

    int npairs = (E < 2048) ? E : 2048;
    int ngrid  = (N + 255) / 256;
    int egrid  = (E + 255) / 256;
    int w64    = (N * 2 + 7) / 8;      // spmm<64>: 2 warps/row, 8 warps/block
    int w32    = (N + 7) / 8;          // spmm<32>: 1 warp/row

    k_init<<<ngrid, 256>>>((const unsigned int*)ei, npairs, N);          // 1
    k_fill_ell<<<egrid, 256>>>(ei, E);                                    // 2
    k_gemm2<64, 0><<<(N + 127) / 128, 256>>>(x, W1, nullptr, g_bufA, N);  // 3
    k_spmm<64><<<w64, 256>>>(g_bufA, g_bufB, N);                          // 4 <- ncu
    k_gemm2<64, 1><<<(N + 127) / 128, 256>>>(g_bufB, W2, b1, g_bufA, N);  // 5
    k_spmm<64><<<w64, 256>>>(g_bufA, g_bufB, N);                          // 6
    k_gemm2<32, 2><<<(N + 255) / 256, 256>>>(g_bufB, W3, b2, g_bufA, N);  // 7
    k_spmm<32><<<w32, 256>>>(g_bufA, g_bufB, N);                          // 8
    k_pool_acc<<<(N * 32 + 255) / 256, 256>>>(g_bufB, batch, N);          // 9
    k_pool_out<<<(G_MAX * 32 + 255) / 256, 256>>>(out, b3);               // 10
}

// round 7
// speedup vs baseline: 14.6110x; 14.6110x over previous
#include <cuda_runtime.h>
#include <cuda_bf16.h>

// ---------------------------------------------------------------------------
// GCN: 3x GCNConv (64->64->64->32) + global mean pool, ONE persistent kernel.
// Phases separated by a software grid barrier (all 296 blocks co-resident).
//   g[i]   = dinv[i] * (act(prev[i] + b) @ W)      dinv = rsqrt(deg+1)
//   out[r] = dinv[r] * (g[r] + sum_{e: dst=r} g[src(e)])
// ---------------------------------------------------------------------------

#define N_MAX 100000
#define E_MAX 1600000
#define G_MAX 64
#define CAP   128
#define FULL  0xffffffffu
#define NBLK  296            // 148 SMs x 2 blocks, guaranteed co-resident

__device__ int   g_is64;
__device__ int   g_cursor[N_MAX];
__device__ int   g_col[(size_t)N_MAX * CAP];
__device__ float g_bufA[(size_t)N_MAX * 64];
__device__ float g_bufB[(size_t)N_MAX * 64];
__device__ float g_sums[G_MAX * 32];
__device__ int   g_cnt[G_MAX];
__device__ int   g_bar_cnt;
__device__ int   g_bar_gen;

__device__ __forceinline__ int load_idx(const void* p, long long i, int is64) {
    if (is64) return (int)(((const long long*)p)[i]);
    return ((const int*)p)[i];
}

// ---- software grid barrier (all NBLK blocks resident) ----------------------
__device__ __forceinline__ void gsync() {
    __syncthreads();
    if (threadIdx.x == 0) {
        int gen = *(volatile int*)&g_bar_gen;
        __threadfence();                       // release my block's stores
        if (atomicAdd(&g_bar_cnt, 1) == NBLK - 1) {
            g_bar_cnt = 0;
            __threadfence();
            *(volatile int*)&g_bar_gen = gen + 1;
        } else {
            while (*(volatile int*)&g_bar_gen == gen) __nanosleep(64);
        }
    }
    __syncthreads();
    __threadfence();   // gpu-scope fence -> CCTL.IVALL: invalidate stale L1
}

// ---- GEMM phase: out[n] = dinv[n]*(act(in[n]+b) @ W), W staged in smem -----
template <int FOUT, int MODE>
__device__ void gemm_phase(const float* __restrict__ in,
                           const float* __restrict__ W,
                           const float* __restrict__ bprev,
                           float* __restrict__ out, int N, float* Ws) {
    for (int i = threadIdx.x; i < 64 * FOUT / 4; i += 256)
        reinterpret_cast<float4*>(Ws)[i] = reinterpret_cast<const float4*>(W)[i];
    __syncthreads();

    const int TPN = FOUT / 32;
    const int NPB = 256 / TPN;
    int half = (TPN == 2) ? (threadIdx.x & 1) : 0;

    for (int n0 = blockIdx.x * NPB; n0 < N; n0 += NBLK * NPB) {
        int n = n0 + threadIdx.x / TPN;
        if (n >= N) continue;

        float acc[32];
#pragma unroll
        for (int j = 0; j < 32; j++) acc[j] = 0.f;

        const float* xr = in + (size_t)n * 64;
        for (int c = 0; c < 4; c++) {
            float4 xv[4];
#pragma unroll
            for (int i = 0; i < 4; i++) {
                xv[i] = *reinterpret_cast<const float4*>(xr + 16 * c + 4 * i);
                if (MODE != 0) {
                    float4 b4 = __ldg(reinterpret_cast<const float4*>(bprev) + 4 * c + i);
                    xv[i].x += b4.x; xv[i].y += b4.y;
                    xv[i].z += b4.z; xv[i].w += b4.w;
                    if (MODE == 1) {
                        xv[i].x = fmaxf(xv[i].x, 0.f); xv[i].y = fmaxf(xv[i].y, 0.f);
                        xv[i].z = fmaxf(xv[i].z, 0.f); xv[i].w = fmaxf(xv[i].w, 0.f);
                    }
                }
            }
            const float* wb = Ws + (size_t)(16 * c) * FOUT + half * 32;
#pragma unroll
            for (int kk = 0; kk < 16; kk++) {
                float xk = reinterpret_cast<const float*>(xv)[kk];
                const float4* wr = reinterpret_cast<const float4*>(wb + kk * FOUT);
#pragma unroll
                for (int j = 0; j < 8; j++) {
                    float4 wv = wr[j];
                    acc[4 * j + 0] += xk * wv.x;
                    acc[4 * j + 1] += xk * wv.y;
                    acc[4 * j + 2] += xk * wv.z;
                    acc[4 * j + 3] += xk * wv.w;
                }
            }
        }

        float dr = rsqrtf((float)(g_cursor[n] + 1));
        float* outp = out + (size_t)n * FOUT + half * 32;
#pragma unroll
        for (int j = 0; j < 8; j++) {
            float4 o = make_float4(dr * acc[4 * j + 0], dr * acc[4 * j + 1],
                                   dr * acc[4 * j + 2], dr * acc[4 * j + 3]);
            *reinterpret_cast<float4*>(outp + 4 * j) = o;
        }
    }
    __syncthreads();    // protect Ws until everyone is done with it
}

// ---- SpMM phase (ELL): warp per (row, 32-feature half) ---------------------
template <int F>
__device__ void spmm_phase(const float* __restrict__ g, float* __restrict__ out,
                           int N) {
    const int WPR = F / 32;
    int lane = threadIdx.x & 31;
    int wib  = threadIdx.x >> 5;
    const int totalWarps = NBLK * 8;

    for (int gw = blockIdx.x * 8 + wib; gw < N * WPR; gw += totalWarps) {
        int row  = (WPR == 2) ? (gw >> 1) : gw;
        int half = (WPR == 2) ? (gw & 1) : 0;

        int degT = g_cursor[row];
        int deg  = (degT < CAP) ? degT : CAP;
        float dr = rsqrtf((float)(degT + 1));

        const float* __restrict__ gb = g + half * 32 + lane;
        float acc = __ldg(&gb[(size_t)row * F]);          // self loop
        const int* cp = g_col + (size_t)row * CAP;

        for (int e = 0; e < deg; e += 32) {
            int nn = deg - e; if (nn > 32) nn = 32;
            int myc = (lane < nn) ? __ldg(&cp[e + lane]) : 0;
            int j = 0;
            for (; j + 8 <= nn; j += 8) {
                int c0 = __shfl_sync(FULL, myc, j + 0);
                int c1 = __shfl_sync(FULL, myc, j + 1);
                int c2 = __shfl_sync(FULL, myc, j + 2);
                int c3 = __shfl_sync(FULL, myc, j + 3);
                int c4 = __shfl_sync(FULL, myc, j + 4);
                int c5 = __shfl_sync(FULL, myc, j + 5);
                int c6 = __shfl_sync(FULL, myc, j + 6);
                int c7 = __shfl_sync(FULL, myc, j + 7);
                float v0 = __ldg(&gb[(size_t)c0 * F]);
                float v1 = __ldg(&gb[(size_t)c1 * F]);
                float v2 = __ldg(&gb[(size_t)c2 * F]);
                float v3 = __ldg(&gb[(size_t)c3 * F]);
                float v4 = __ldg(&gb[(size_t)c4 * F]);
                float v5 = __ldg(&gb[(size_t)c5 * F]);
                float v6 = __ldg(&gb[(size_t)c6 * F]);
                float v7 = __ldg(&gb[(size_t)c7 * F]);
                float s0 = v0 + v1, s1 = v2 + v3, s2 = v4 + v5, s3 = v6 + v7;
                acc += (s0 + s1) + (s2 + s3);
            }
            for (; j < nn; j++) {
                int c = __shfl_sync(FULL, myc, j);
                acc += __ldg(&gb[(size_t)c * F]);
            }
        }
        out[(size_t)row * F + half * 32 + lane] = dr * acc;
    }
}

// ---- the one persistent kernel ---------------------------------------------
__global__ __launch_bounds__(256, 2)
void k_gcn_fused(const float* __restrict__ x, const void* ei, const void* batch,
                 const float* __restrict__ W1, const float* __restrict__ b1,
                 const float* __restrict__ W2, const float* __restrict__ b2,
                 const float* __restrict__ W3, const float* __restrict__ b3,
                 float* __restrict__ out, int N, int E, int npairs) {
    __shared__ float Ws[64 * 64];
    int gtid   = blockIdx.x * 256 + threadIdx.x;
    int stride = NBLK * 256;

    // P0: zero scratch + dtype detect
    for (int i = gtid; i < N; i += stride) g_cursor[i] = 0;
    if (gtid < G_MAX * 32) g_sums[gtid] = 0.0f;
    if (gtid < G_MAX) g_cnt[gtid] = 0;
    if (blockIdx.x == 0) {
        __shared__ int any;
        if (threadIdx.x == 0) any = 0;
        __syncthreads();
        const unsigned int* w = (const unsigned int*)ei;
        for (int k = threadIdx.x; k < npairs; k += 256)
            if (w[2 * k + 1] != 0u) any = 1;
        __syncthreads();
        if (threadIdx.x == 0) g_is64 = (any == 0) ? 1 : 0;
    }
    gsync();

    // P1: ELL fill
    {
        int is64 = g_is64;
        for (int e = gtid; e < E; e += stride) {
            int s = load_idx(ei, e, is64);
            int d = load_idx(ei, (long long)E + e, is64);
            int pos = atomicAdd(&g_cursor[d], 1);
            if (pos < CAP) g_col[(size_t)d * CAP + pos] = s;
        }
    }
    gsync();

    // P2..P7: three (gemm, spmm) layers
    gemm_phase<64, 0>(x, W1, nullptr, g_bufA, N, Ws);
    gsync();
    spmm_phase<64>(g_bufA, g_bufB, N);
    gsync();
    gemm_phase<64, 1>(g_bufB, W2, b1, g_bufA, N, Ws);
    gsync();
    spmm_phase<64>(g_bufA, g_bufB, N);
    gsync();
    gemm_phase<32, 2>(g_bufB, W3, b2, g_bufA, N, Ws);
    gsync();
    spmm_phase<32>(g_bufA, g_bufB, N);
    gsync();

    // P8: pool accumulate
    {
        int is64 = g_is64;
        for (int idx = gtid; idx < N * 32; idx += stride) {
            int n = idx >> 5;
            int f = idx & 31;
            int b = load_idx(batch, n, is64);
            atomicAdd(&g_sums[b * 32 + f], g_bufB[(size_t)n * 32 + f]);
            if (f == 0) atomicAdd(&g_cnt[b], 1);
        }
    }
    gsync();

    // P9: write output
    if (gtid < G_MAX * 32) {
        int f = gtid & 31;
        float c = fmaxf((float)g_cnt[gtid >> 5], 1.0f);
        out[gtid] = g_sums[gtid] / c + __ldg(&b3[f]);
    }
}

// ---------------------------------------------------------------------------
extern "C" void kernel_launch(void* const* d_in, const int* in_sizes, int n_in,
                              void* d_out, int out_size) {
    int N = in_sizes[0] / 64;
    int E = in_sizes[1] / 2;
    if (N > N_MAX) N = N_MAX;
    if (E > E_MAX) E = E_MAX;

    int base = 3;
    if (n_in >= 10 && in_sizes[3] == 1) base = 4;

    const float* x     = (const float*)d_in[0];
    const void*  ei    = d_in[1];
    const void*  batch = d_in[2];
    const float* W1 = (const float*)d_in[base + 0];
    const float* b1 = (const float*)d_in[base + 1];
    const float* W2 = (const float*)d_in[base + 2];
    const float* b2 = (const float*)d_in[base + 3];
    const float* W3 = (const float*)d_in[base + 4];
    const float* b3 = (const float*)d_in[base + 5];
    float* out = (float*)d_out;

    int npairs = (E < 2048) ? E : 2048;

    k_gcn_fused<<<NBLK, 256>>>(x, ei, batch, W1, b1, W2, b2, W3, b3,
                               out, N, E, npairs);
}

// round 10
// speedup vs baseline: 15.3154x; 1.0482x over previous
#include <cuda_runtime.h>
#include <cuda_bf16.h>

// ---------------------------------------------------------------------------
// GCN: 3x GCNConv (64->64->64->32) + global mean pool, ONE persistent kernel.
// 444 co-resident blocks (148 SM x 3), software grid barriers between phases.
//   g[i]   = dinv[i] * (act(prev[i] + b) @ W)      dinv = rsqrt(deg+1)
//   out[r] = dinv[r] * (g[r] + sum_{e: dst=r} g[src(e)])
// ---------------------------------------------------------------------------

#define N_MAX 100000
#define E_MAX 1600000
#define G_MAX 64
#define CAP   128
#define FULL  0xffffffffu
#define NBLK  444            // 148 SMs x 3 blocks, co-resident (<=85 regs)

__device__ int   g_cursor[N_MAX];
__device__ int   g_col[(size_t)N_MAX * CAP];
__device__ float g_bufA[(size_t)N_MAX * 64];
__device__ float g_bufB[(size_t)N_MAX * 64];
__device__ float g_sums[G_MAX * 32];
__device__ int   g_cnt[G_MAX];
__device__ int   g_bar_cnt;
__device__ int   g_bar_gen;

__device__ __forceinline__ int load_idx(const void* p, long long i, int is64) {
    if (is64) return (int)(((const long long*)p)[i]);
    return ((const int*)p)[i];
}

// ---- software grid barrier (all NBLK blocks resident) ----------------------
__device__ __forceinline__ void gsync() {
    __syncthreads();
    if (threadIdx.x == 0) {
        int gen = *(volatile int*)&g_bar_gen;
        __threadfence();
        if (atomicAdd(&g_bar_cnt, 1) == NBLK - 1) {
            g_bar_cnt = 0;
            __threadfence();
            *(volatile int*)&g_bar_gen = gen + 1;
        } else {
            while (*(volatile int*)&g_bar_gen == gen) __nanosleep(64);
        }
    }
    __syncthreads();
    __threadfence();   // gpu-scope -> CCTL.IVALL: drop stale L1 lines
}

// ---- GEMM phase: out[n] = dinv[n]*(act(in[n]+b) @ W) -----------------------
// TPN threads per node, each computes FOUT/TPN = 16 outputs. W in smem.
template <int FOUT, int MODE>
__device__ void gemm_phase(const float* __restrict__ in,
                           const float* __restrict__ W,
                           const float* __restrict__ bprev,
                           float* __restrict__ out, int N, float* Ws) {
    for (int i = threadIdx.x; i < 64 * FOUT / 4; i += 256)
        reinterpret_cast<float4*>(Ws)[i] = reinterpret_cast<const float4*>(W)[i];
    __syncthreads();

    const int TPN = FOUT / 16;              // 4 (F=64) or 2 (F=32)
    const int NPB = 256 / TPN;
    int part = threadIdx.x & (TPN - 1);     // which 16-feature slice

    for (int n0 = blockIdx.x * NPB; n0 < N; n0 += NBLK * NPB) {
        int n = n0 + threadIdx.x / TPN;
        if (n >= N) continue;

        float acc[16];
#pragma unroll
        for (int j = 0; j < 16; j++) acc[j] = 0.f;

        const float* xr = in + (size_t)n * 64;
#pragma unroll
        for (int c = 0; c < 4; c++) {
            float4 xv[4];
#pragma unroll
            for (int i = 0; i < 4; i++) {
                xv[i] = *reinterpret_cast<const float4*>(xr + 16 * c + 4 * i);
                if (MODE != 0) {
                    float4 b4 = __ldg(reinterpret_cast<const float4*>(bprev) + 4 * c + i);
                    xv[i].x += b4.x; xv[i].y += b4.y;
                    xv[i].z += b4.z; xv[i].w += b4.w;
                    if (MODE == 1) {
                        xv[i].x = fmaxf(xv[i].x, 0.f); xv[i].y = fmaxf(xv[i].y, 0.f);
                        xv[i].z = fmaxf(xv[i].z, 0.f); xv[i].w = fmaxf(xv[i].w, 0.f);
                    }
                }
            }
            const float* wb = Ws + (size_t)(16 * c) * FOUT + part * 16;
#pragma unroll
            for (int kk = 0; kk < 16; kk++) {
                float xk = reinterpret_cast<const float*>(xv)[kk];
                const float4* wr = reinterpret_cast<const float4*>(wb + kk * FOUT);
#pragma unroll
                for (int j = 0; j < 4; j++) {
                    float4 wv = wr[j];
                    acc[4 * j + 0] += xk * wv.x;
                    acc[4 * j + 1] += xk * wv.y;
                    acc[4 * j + 2] += xk * wv.z;
                    acc[4 * j + 3] += xk * wv.w;
                }
            }
        }

        float dr = rsqrtf((float)(g_cursor[n] + 1));
        float* outp = out + (size_t)n * FOUT + part * 16;
#pragma unroll
        for (int j = 0; j < 4; j++) {
            float4 o = make_float4(dr * acc[4 * j + 0], dr * acc[4 * j + 1],
                                   dr * acc[4 * j + 2], dr * acc[4 * j + 3]);
            *reinterpret_cast<float4*>(outp + 4 * j) = o;
        }
    }
    __syncthreads();    // protect Ws until all warps done
}

// ---- SpMM phase (ELL): warp per (row, 32-feature half), 16 loads in flight -
template <int F>
__device__ void spmm_phase(const float* __restrict__ g, float* __restrict__ out,
                           int N) {
    const int WPR = F / 32;
    int lane = threadIdx.x & 31;
    int wib  = threadIdx.x >> 5;
    const int totalWarps = NBLK * 8;

    for (int gw = blockIdx.x * 8 + wib; gw < N * WPR; gw += totalWarps) {
        int row  = (WPR == 2) ? (gw >> 1) : gw;
        int half = (WPR == 2) ? (gw & 1) : 0;

        int degT = g_cursor[row];
        int deg  = (degT < CAP) ? degT : CAP;
        float dr = rsqrtf((float)(degT + 1));

        const float* __restrict__ gb = g + half * 32 + lane;
        float acc = __ldg(&gb[(size_t)row * F]);          // self loop
        const int* cp = g_col + (size_t)row * CAP;

        for (int e = 0; e < deg; e += 32) {
            int nn = deg - e; if (nn > 32) nn = 32;
            int myc = (lane < nn) ? __ldg(&cp[e + lane]) : 0;
            int j = 0;
            for (; j + 16 <= nn; j += 16) {
                float v[16];
#pragma unroll
                for (int q = 0; q < 16; q++) {
                    int c = __shfl_sync(FULL, myc, j + q);
                    v[q] = __ldg(&gb[(size_t)c * F]);
                }
                float s0 = (v[0] + v[1]) + (v[2] + v[3]);
                float s1 = (v[4] + v[5]) + (v[6] + v[7]);
                float s2 = (v[8] + v[9]) + (v[10] + v[11]);
                float s3 = (v[12] + v[13]) + (v[14] + v[15]);
                acc += (s0 + s1) + (s2 + s3);
            }
            for (; j + 4 <= nn; j += 4) {
                int c0 = __shfl_sync(FULL, myc, j + 0);
                int c1 = __shfl_sync(FULL, myc, j + 1);
                int c2 = __shfl_sync(FULL, myc, j + 2);
                int c3 = __shfl_sync(FULL, myc, j + 3);
                float v0 = __ldg(&gb[(size_t)c0 * F]);
                float v1 = __ldg(&gb[(size_t)c1 * F]);
                float v2 = __ldg(&gb[(size_t)c2 * F]);
                float v3 = __ldg(&gb[(size_t)c3 * F]);
                acc += (v0 + v1) + (v2 + v3);
            }
            for (; j < nn; j++) {
                int c = __shfl_sync(FULL, myc, j);
                acc += __ldg(&gb[(size_t)c * F]);
            }
        }
        out[(size_t)row * F + half * 32 + lane] = dr * acc;
    }
}

// ---- the one persistent kernel ---------------------------------------------
__global__ __launch_bounds__(256, 3)
void k_gcn_fused(const float* __restrict__ x, const void* ei, const void* batch,
                 const float* __restrict__ W1, const float* __restrict__ b1,
                 const float* __restrict__ W2, const float* __restrict__ b2,
                 const float* __restrict__ W3, const float* __restrict__ b3,
                 float* __restrict__ out, int N, int E, int npairs) {
    __shared__ float Ws[64 * 64];
    __shared__ int sh_any;
    int gtid   = blockIdx.x * 256 + threadIdx.x;
    int stride = NBLK * 256;

    // P0: zero scratch; every block detects dtype for itself (no barrier dep)
    if (threadIdx.x == 0) sh_any = 0;
    __syncthreads();
    for (int i = gtid; i < N; i += stride) g_cursor[i] = 0;
    if (gtid < G_MAX * 32) g_sums[gtid] = 0.0f;
    if (gtid < G_MAX) g_cnt[gtid] = 0;
    {
        const unsigned int* w = (const unsigned int*)ei;
        int local = 0;
        for (int k = threadIdx.x; k < npairs; k += 256)
            if (w[2 * k + 1] != 0u) local = 1;
        if (local) sh_any = 1;
    }
    __syncthreads();
    int is64 = (sh_any == 0) ? 1 : 0;
    gsync();

    // P1: ELL fill
    for (int e = gtid; e < E; e += stride) {
        int s = load_idx(ei, e, is64);
        int d = load_idx(ei, (long long)E + e, is64);
        int pos = atomicAdd(&g_cursor[d], 1);
        if (pos < CAP) g_col[(size_t)d * CAP + pos] = s;
    }
    gsync();

    // P2..P7: three (gemm, spmm) layers
    gemm_phase<64, 0>(x, W1, nullptr, g_bufA, N, Ws);
    gsync();
    spmm_phase<64>(g_bufA, g_bufB, N);
    gsync();
    gemm_phase<64, 1>(g_bufB, W2, b1, g_bufA, N, Ws);
    gsync();
    spmm_phase<64>(g_bufA, g_bufB, N);
    gsync();
    gemm_phase<32, 2>(g_bufB, W3, b2, g_bufA, N, Ws);
    gsync();
    spmm_phase<32>(g_bufA, g_bufB, N);
    gsync();

    // P8: pool accumulate
    for (int idx = gtid; idx < N * 32; idx += stride) {
        int n = idx >> 5;
        int f = idx & 31;
        int b = load_idx(batch, n, is64);
        atomicAdd(&g_sums[b * 32 + f], g_bufB[(size_t)n * 32 + f]);
        if (f == 0) atomicAdd(&g_cnt[b], 1);
    }
    gsync();

    // P9: write output
    if (gtid < G_MAX * 32) {
        int f = gtid & 31;
        float c = fmaxf((float)g_cnt[gtid >> 5], 1.0f);
        out[gtid] = g_sums[gtid] / c + __ldg(&b3[f]);
    }
}

// ---------------------------------------------------------------------------
extern "C" void kernel_launch(void* const* d_in, const int* in_sizes, int n_in,
                              void* d_out, int out_size) {
    int N = in_sizes[0] / 64;
    int E = in_sizes[1] / 2;
    if (N > N_MAX) N = N_MAX;
    if (E > E_MAX) E = E_MAX;

    int base = 3;
    if (n_in >= 10 && in_sizes[3] == 1) base = 4;

    const float* x     = (const float*)d_in[0];
    const void*  ei    = d_in[1];
    const void*  batch = d_in[2];
    const float* W1 = (const float*)d_in[base + 0];
    const float* b1 = (const float*)d_in[base + 1];
    const float* W2 = (const float*)d_in[base + 2];
    const float* b2 = (const float*)d_in[base + 3];
    const float* W3 = (const float*)d_in[base + 4];
    const float* b3 = (const float*)d_in[base + 5];
    float* out = (float*)d_out;

    int npairs = (E < 2048) ? E : 2048;

    k_gcn_fused<<<NBLK, 256>>>(x, ei, batch, W1, b1, W2, b2, W3, b3,
                               out, N, E, npairs);
}